// round 1
// baseline (speedup 1.0000x reference)
#include <cuda_runtime.h>

// MaxAssigner2D: out[b,h,w] = max over taps {(0,0),(-1,0),(-2,0),(0,-1),(0,-2),(-1,-1),(-2,-2)}
// of channel-max(x[b, h+dh, w+dw, :]), with out-of-image positions contributing 0
// (zero padding in the reference). x: [16,512,512,32] f32, out: [16,512,512,1] f32.

#define BATCH 16
#define HGT   512
#define WID   512
#define CH    32
#define TH    32              // output rows per block
#define HALO  2
#define TROWS (TH + HALO)     // 34 xc rows staged
#define SW    (WID + HALO)    // 514 smem cols (2 left-halo zeros)
#define NTHREADS 512

__global__ void __launch_bounds__(NTHREADS, 3)
maxassigner2d_kernel(const float* __restrict__ x, float* __restrict__ out)
{
    extern __shared__ float s_xc[];   // [TROWS][SW]

    const int tid  = threadIdx.x;
    const int img  = blockIdx.x / (HGT / TH);
    const int tile = blockIdx.x % (HGT / TH);
    const int row0 = tile * TH;       // first output row of this block

    // Zero the 2 left-halo columns (always out-of-image since blocks span full width)
    if (tid < TROWS * HALO) {
        int r = tid / HALO, c = tid % HALO;
        s_xc[r * SW + c] = 0.0f;
    }

    const int lane = tid & 31;
    const int warp = tid >> 5;
    const int sub  = lane >> 3;       // which of 4 pixels this warp-eighth handles
    const int chq  = lane & 7;        // which float4 (8 x float4 = 32 channels)

    // ---- Fill phase: compute channel-max for TROWS x WID pixels ----
    // Each group of 8 lanes handles one pixel: 8 coalesced LDG.128 + shfl reduce.
    const int total = TROWS * WID;
    #pragma unroll 4
    for (int p = warp * 4 + sub; p < total; p += (NTHREADS / 8)) {
        const int lr = p >> 9;            // p / WID
        const int c  = p & (WID - 1);     // p % WID
        const int g  = row0 + lr - HALO;  // global image row (may be < 0 at top)
        float v = 0.0f;
        if (g >= 0) {
            const float4* ptr =
                (const float4*)(x + ((((size_t)img * HGT + g) * WID + c) * CH)) + chq;
            float4 d = __ldg(ptr);
            v = fmaxf(fmaxf(d.x, d.y), fmaxf(d.z, d.w));
        }
        v = fmaxf(v, __shfl_xor_sync(0xffffffffu, v, 1));
        v = fmaxf(v, __shfl_xor_sync(0xffffffffu, v, 2));
        v = fmaxf(v, __shfl_xor_sync(0xffffffffu, v, 4));
        if (chq == 0) s_xc[lr * SW + HALO + c] = v;
    }
    __syncthreads();

    // ---- Stencil + store phase: 7 taps from smem, coalesced row stores ----
    const int c = tid;  // column 0..511 (NTHREADS == WID)
    float* orow = out + (((size_t)img * HGT + row0) * WID + c);
    #pragma unroll 4
    for (int r = 0; r < TH; r++) {
        const float* s0 = s_xc + r * SW + c;  // global row (h-2), base at smem col c
        const float* s1 = s0 + SW;            // (h-1)
        const float* s2 = s1 + SW;            // (h)
        float m = s2[HALO];                   // ( 0, 0)
        m = fmaxf(m, s1[HALO]);               // (-1, 0)
        m = fmaxf(m, s0[HALO]);               // (-2, 0)
        m = fmaxf(m, s2[HALO - 1]);           // ( 0,-1)
        m = fmaxf(m, s2[HALO - 2]);           // ( 0,-2)
        m = fmaxf(m, s1[HALO - 1]);           // (-1,-1)
        m = fmaxf(m, s0[HALO - 2]);           // (-2,-2)
        orow[(size_t)r * WID] = m;
    }
}

extern "C" void kernel_launch(void* const* d_in, const int* in_sizes, int n_in,
                              void* d_out, int out_size)
{
    (void)in_sizes; (void)n_in; (void)out_size;
    const float* x = (const float*)d_in[0];
    float* out = (float*)d_out;

    const int smem_bytes = TROWS * SW * sizeof(float);  // 69,904 B > 48KB -> opt-in
    cudaFuncSetAttribute(maxassigner2d_kernel,
                         cudaFuncAttributeMaxDynamicSharedMemorySize, smem_bytes);

    dim3 grid(BATCH * (HGT / TH));   // 16 * 16 = 256 blocks
    maxassigner2d_kernel<<<grid, NTHREADS, smem_bytes>>>(x, out);
}

// round 2
// speedup vs baseline: 1.1935x; 1.1935x over previous
#include <cuda_runtime.h>

// MaxAssigner2D, two-phase:
//   Phase 1 (streaming): xc[p] = max over 32 channels of x[p*32 .. p*32+31]
//   Phase 2 (stencil):   out[b,h,w] = max over taps
//       {(0,0),(-1,0),(-2,0),(0,-1),(0,-2),(-1,-1),(-2,-2)} of xc[b,h+dh,w+dw]
//   with out-of-image taps contributing 0 (zero pad in reference).
// x: [16,512,512,32] f32  ->  out: [16,512,512,1] f32

#define BATCH 16
#define HGT   512
#define WID   512
#define CH    32
#define NPIX  (BATCH * HGT * WID)   // 4,194,304

// 16 MB scratch for channel-max image (device global: allocation-free)
__device__ float g_xc[NPIX];

// ---------------- Phase 1: channel-max, pure streaming ----------------
// 8 lanes per pixel: one coalesced LDG.128 each (512B contiguous per warp),
// shfl-xor reduce over the 8-lane group. Exact trip count, no predicates.
#define K1_NT      256
#define K1_BLOCKS  2048
#define K1_GROUPS  (K1_BLOCKS * K1_NT / 8)        // 65,536 pixel groups / sweep
#define K1_ITERS   (NPIX / K1_GROUPS)             // 64, exact

__global__ void __launch_bounds__(K1_NT)
chanmax_kernel(const float* __restrict__ x)
{
    const int tid  = blockIdx.x * K1_NT + threadIdx.x;
    const int gid  = tid >> 3;          // pixel-group id
    const int chq  = tid & 7;           // which float4 of the 32 channels

    #pragma unroll 4
    for (int it = 0; it < K1_ITERS; it++) {
        const int p = it * K1_GROUPS + gid;
        const float4 d = __ldg((const float4*)(x + (size_t)p * CH) + chq);
        float v = fmaxf(fmaxf(d.x, d.y), fmaxf(d.z, d.w));
        v = fmaxf(v, __shfl_xor_sync(0xffffffffu, v, 1));
        v = fmaxf(v, __shfl_xor_sync(0xffffffffu, v, 2));
        v = fmaxf(v, __shfl_xor_sync(0xffffffffu, v, 4));
        if (chq == 0) g_xc[p] = v;
    }
}

// ---------------- Phase 2: 7-tap stencil on xc ----------------
#define TH    16
#define HALO  2
#define TROWS (TH + HALO)        // 18
#define SW    (WID + HALO)       // 514
#define K2_NT 512

__global__ void __launch_bounds__(K2_NT)
stencil_kernel(float* __restrict__ out)
{
    __shared__ float s[TROWS * SW];    // 37,008 B (< 48 KB, no opt-in)

    const int tid  = threadIdx.x;
    const int img  = blockIdx.x / (HGT / TH);
    const int tile = blockIdx.x % (HGT / TH);
    const int row0 = tile * TH;

    // zero the 2 left-halo columns
    if (tid < TROWS * HALO) {
        int r = tid / HALO, c = tid % HALO;
        s[r * SW + c] = 0.0f;
    }

    // load 18 rows x 512 cols of xc (top halo may be out-of-image -> 0)
    const float* xc_img = g_xc + (size_t)img * HGT * WID;
    #pragma unroll
    for (int r = 0; r < TROWS; r++) {
        const int g = row0 + r - HALO;
        s[r * SW + HALO + tid] = (g >= 0) ? __ldg(xc_img + (size_t)g * WID + tid) : 0.0f;
    }
    __syncthreads();

    float* orow = out + (((size_t)img * HGT + row0) * WID + tid);
    #pragma unroll
    for (int r = 0; r < TH; r++) {
        const float* s0 = s + r * SW + tid;   // row (h-2)
        const float* s1 = s0 + SW;            // row (h-1)
        const float* s2 = s1 + SW;            // row (h)
        float m = s2[HALO];                   // ( 0, 0)
        m = fmaxf(m, s1[HALO]);               // (-1, 0)
        m = fmaxf(m, s0[HALO]);               // (-2, 0)
        m = fmaxf(m, s2[HALO - 1]);           // ( 0,-1)
        m = fmaxf(m, s2[HALO - 2]);           // ( 0,-2)
        m = fmaxf(m, s1[HALO - 1]);           // (-1,-1)
        m = fmaxf(m, s0[HALO - 2]);           // (-2,-2)
        orow[(size_t)r * WID] = m;
    }
}

extern "C" void kernel_launch(void* const* d_in, const int* in_sizes, int n_in,
                              void* d_out, int out_size)
{
    (void)in_sizes; (void)n_in; (void)out_size;
    const float* x = (const float*)d_in[0];
    float* out = (float*)d_out;

    chanmax_kernel<<<K1_BLOCKS, K1_NT>>>(x);
    stencil_kernel<<<BATCH * (HGT / TH), K2_NT>>>(out);
}